// round 1
// baseline (speedup 1.0000x reference)
#include <cuda_runtime.h>
#include <cuda_bf16.h>
#include <math_constants.h>

// Problem constants
#define B_SZ    2
#define N_SEQ   2048
#define DMODEL  2048
#define HQ      32
#define HKV     8
#define DHEAD   64
#define QKV_DIM 3072          // DHEAD * (HQ + 2*HKV)
#define TOKENS  4096          // B_SZ * N_SEQ
#define NH_NORM (HQ + HKV)    // heads that get norm+rope

// Scratch (allocation-free: device globals)
__device__ float g_qkv[(size_t)TOKENS * QKV_DIM];   // 48 MB
__device__ float g_y[(size_t)TOKENS * DMODEL];      // 32 MB

// ---------------------------------------------------------------------------
// GEMM: C[M,N] = A[M,K] * B[N,K]^T   (both inputs K-major, fp32)
// 64x64 tile, BK=16, 256 threads, 4x4 register block per thread.
// ---------------------------------------------------------------------------
__global__ __launch_bounds__(256) void gemm_nt(const float* __restrict__ A,
                                               const float* __restrict__ Bm,
                                               float* __restrict__ C,
                                               int M, int N, int K) {
    const int BK = 16;
    __shared__ float As[16][65];   // [k][m], padded
    __shared__ float Bs[16][65];   // [k][n], padded

    int tid = threadIdx.x;
    int tx = tid & 15, ty = tid >> 4;
    int bm = blockIdx.y * 64, bn = blockIdx.x * 64;

    int lrow = tid >> 2;          // 0..63
    int lk   = (tid & 3) << 2;    // 0,4,8,12

    const float* Ap = A + (size_t)(bm + lrow) * K + lk;
    const float* Bp = Bm + (size_t)(bn + lrow) * K + lk;

    float acc[4][4];
#pragma unroll
    for (int a = 0; a < 4; a++)
#pragma unroll
        for (int c = 0; c < 4; c++) acc[a][c] = 0.f;

    for (int k0 = 0; k0 < K; k0 += BK) {
        float4 va = *(const float4*)(Ap + k0);
        float4 vb = *(const float4*)(Bp + k0);
        As[lk + 0][lrow] = va.x; As[lk + 1][lrow] = va.y;
        As[lk + 2][lrow] = va.z; As[lk + 3][lrow] = va.w;
        Bs[lk + 0][lrow] = vb.x; Bs[lk + 1][lrow] = vb.y;
        Bs[lk + 2][lrow] = vb.z; Bs[lk + 3][lrow] = vb.w;
        __syncthreads();
#pragma unroll
        for (int kk = 0; kk < BK; kk++) {
            float a0 = As[kk][ty * 4 + 0];
            float a1 = As[kk][ty * 4 + 1];
            float a2 = As[kk][ty * 4 + 2];
            float a3 = As[kk][ty * 4 + 3];
            float b0 = Bs[kk][tx * 4 + 0];
            float b1 = Bs[kk][tx * 4 + 1];
            float b2 = Bs[kk][tx * 4 + 2];
            float b3 = Bs[kk][tx * 4 + 3];
            acc[0][0] += a0 * b0; acc[0][1] += a0 * b1; acc[0][2] += a0 * b2; acc[0][3] += a0 * b3;
            acc[1][0] += a1 * b0; acc[1][1] += a1 * b1; acc[1][2] += a1 * b2; acc[1][3] += a1 * b3;
            acc[2][0] += a2 * b0; acc[2][1] += a2 * b1; acc[2][2] += a2 * b2; acc[2][3] += a2 * b3;
            acc[3][0] += a3 * b0; acc[3][1] += a3 * b1; acc[3][2] += a3 * b2; acc[3][3] += a3 * b3;
        }
        __syncthreads();
    }

#pragma unroll
    for (int a = 0; a < 4; a++) {
        float4 v = make_float4(acc[a][0], acc[a][1], acc[a][2], acc[a][3]);
        *(float4*)&C[(size_t)(bm + ty * 4 + a) * N + bn + tx * 4] = v;
    }
}

// ---------------------------------------------------------------------------
// Fused per-head RMSNorm + RoPE, in place on g_qkv. One warp per (token, head).
// Lane l owns dims l and l+32 (the RoPE pair), freq index = l.
// ---------------------------------------------------------------------------
__global__ void norm_rope_kernel(const int* __restrict__ pos,
                                 const float* __restrict__ qw,
                                 const float* __restrict__ kw) {
    int gw = (blockIdx.x * blockDim.x + threadIdx.x) >> 5;
    int lane = threadIdx.x & 31;
    if (gw >= TOKENS * NH_NORM) return;
    int token = gw / NH_NORM;
    int h = gw - token * NH_NORM;          // 0..31 q heads, 32..39 k heads (same qkv slot)
    int p = pos[token & (N_SEQ - 1)];

    float* ptr = g_qkv + (size_t)token * QKV_DIM + h * DHEAD;
    float x1 = ptr[lane];
    float x2 = ptr[lane + 32];
    float ss = x1 * x1 + x2 * x2;
#pragma unroll
    for (int o = 16; o; o >>= 1) ss += __shfl_xor_sync(0xffffffffu, ss, o);
    float r = rsqrtf(ss * (1.0f / 64.0f) + 1e-6f);
    const float* w = (h < HQ) ? qw : kw;
    x1 *= r * w[lane];
    x2 *= r * w[lane + 32];

    // inv_freq = 10000^(-2*lane/64)
    float inv = expf(-(float)(2 * lane) * (9.210340371976184f / 64.0f));
    float sv, cv;
    sincosf((float)p * inv, &sv, &cv);
    ptr[lane]      = x1 * cv - x2 * sv;
    ptr[lane + 32] = x1 * sv + x2 * cv;
}

// ---------------------------------------------------------------------------
// Causal GQA flash attention, fp32. One block per (64-query tile, q-head, batch).
// 256 threads = 16x16, 4x4 S microtile per thread; online softmax with
// half-warp shfl reductions (the 16 lanes sharing ty own the same 4 rows).
// ---------------------------------------------------------------------------
#define ATTN_SMEM_FLOATS (64 * 65 * 2 + 64 * 64 * 2)
#define ATTN_SMEM_BYTES  (ATTN_SMEM_FLOATS * 4)

__global__ __launch_bounds__(256) void attn_kernel() {
    extern __shared__ float sm[];
    float* Qs = sm;                 // transposed [d][row], stride 65
    float* Ks = Qs + 64 * 65;       // transposed [d][col], stride 65
    float* Vs = Ks + 64 * 65;       // [j][d], stride 64
    float* Ps = Vs + 64 * 64;       // [row][col], stride 64

    int qb = blockIdx.x, h = blockIdx.y, b = blockIdx.z;
    int hk = h >> 2;                // G = 4
    int tid = threadIdx.x;
    int tx = tid & 15, ty = tid >> 4;
    int r0 = ty * 4, c0 = tx * 4;
    int q0 = qb * 64;
    size_t base = (size_t)b * N_SEQ;
    const float scale = 0.125f;     // 64^-0.5

    // Load+transpose Q tile, pre-scaled
    for (int i = tid; i < 64 * 64; i += 256) {
        int row = i >> 6, d = i & 63;
        Qs[d * 65 + row] = g_qkv[(base + q0 + row) * QKV_DIM + h * DHEAD + d] * scale;
    }

    float m[4], l[4], acc[4][4];
#pragma unroll
    for (int a = 0; a < 4; a++) {
        m[a] = -CUDART_INF_F; l[a] = 0.f;
#pragma unroll
        for (int c = 0; c < 4; c++) acc[a][c] = 0.f;
    }

    for (int kb = 0; kb <= qb; kb++) {
        __syncthreads();   // prior-iteration Ps/Vs reads complete
        for (int i = tid; i < 64 * 64; i += 256) {
            int row = i >> 6, d = i & 63;
            size_t toff = (base + kb * 64 + row) * QKV_DIM;
            Ks[d * 65 + row] = g_qkv[toff + (HQ + hk) * DHEAD + d];
            Vs[row * 64 + d] = g_qkv[toff + (HQ + HKV + hk) * DHEAD + d];
        }
        __syncthreads();

        // S = (Q*scale) K^T, 4x4 per thread
        float s4[4][4];
#pragma unroll
        for (int a = 0; a < 4; a++)
#pragma unroll
            for (int c = 0; c < 4; c++) s4[a][c] = 0.f;
#pragma unroll 4
        for (int d = 0; d < 64; d++) {
            float a0 = Qs[d * 65 + r0 + 0];
            float a1 = Qs[d * 65 + r0 + 1];
            float a2 = Qs[d * 65 + r0 + 2];
            float a3 = Qs[d * 65 + r0 + 3];
            float b0 = Ks[d * 65 + c0 + 0];
            float b1 = Ks[d * 65 + c0 + 1];
            float b2 = Ks[d * 65 + c0 + 2];
            float b3 = Ks[d * 65 + c0 + 3];
            s4[0][0] += a0 * b0; s4[0][1] += a0 * b1; s4[0][2] += a0 * b2; s4[0][3] += a0 * b3;
            s4[1][0] += a1 * b0; s4[1][1] += a1 * b1; s4[1][2] += a1 * b2; s4[1][3] += a1 * b3;
            s4[2][0] += a2 * b0; s4[2][1] += a2 * b1; s4[2][2] += a2 * b2; s4[2][3] += a2 * b3;
            s4[3][0] += a3 * b0; s4[3][1] += a3 * b1; s4[3][2] += a3 * b2; s4[3][3] += a3 * b3;
        }

        // Causal mask (only the diagonal block is partial)
        if (kb == qb) {
#pragma unroll
            for (int a = 0; a < 4; a++)
#pragma unroll
                for (int c = 0; c < 4; c++)
                    if (c0 + c > r0 + a) s4[a][c] = -1e30f;
        }

        // Online softmax per row (reduce over the 16 lanes sharing ty)
#pragma unroll
        for (int a = 0; a < 4; a++) {
            float mx = fmaxf(fmaxf(s4[a][0], s4[a][1]), fmaxf(s4[a][2], s4[a][3]));
#pragma unroll
            for (int o = 8; o; o >>= 1)
                mx = fmaxf(mx, __shfl_xor_sync(0xffffffffu, mx, o));
            float mn = fmaxf(m[a], mx);
            float corr = __expf(m[a] - mn);
            float sum = 0.f;
#pragma unroll
            for (int c = 0; c < 4; c++) {
                s4[a][c] = __expf(s4[a][c] - mn);
                sum += s4[a][c];
            }
#pragma unroll
            for (int o = 8; o; o >>= 1)
                sum += __shfl_xor_sync(0xffffffffu, sum, o);
            l[a] = l[a] * corr + sum;
            m[a] = mn;
#pragma unroll
            for (int c = 0; c < 4; c++) acc[a][c] *= corr;
            // stage P for the PV product
#pragma unroll
            for (int c = 0; c < 4; c++) Ps[(r0 + a) * 64 + c0 + c] = s4[a][c];
        }
        __syncthreads();

        // O += P @ V  (thread owns rows r0.., dims c0..)
#pragma unroll 4
        for (int j = 0; j < 64; j++) {
            float p0 = Ps[(r0 + 0) * 64 + j];
            float p1 = Ps[(r0 + 1) * 64 + j];
            float p2 = Ps[(r0 + 2) * 64 + j];
            float p3 = Ps[(r0 + 3) * 64 + j];
            float v0 = Vs[j * 64 + c0 + 0];
            float v1 = Vs[j * 64 + c0 + 1];
            float v2 = Vs[j * 64 + c0 + 2];
            float v3 = Vs[j * 64 + c0 + 3];
            acc[0][0] += p0 * v0; acc[0][1] += p0 * v1; acc[0][2] += p0 * v2; acc[0][3] += p0 * v3;
            acc[1][0] += p1 * v0; acc[1][1] += p1 * v1; acc[1][2] += p1 * v2; acc[1][3] += p1 * v3;
            acc[2][0] += p2 * v0; acc[2][1] += p2 * v1; acc[2][2] += p2 * v2; acc[2][3] += p2 * v3;
            acc[3][0] += p3 * v0; acc[3][1] += p3 * v1; acc[3][2] += p3 * v2; acc[3][3] += p3 * v3;
        }
    }

    // Epilogue: normalize, write y laid out [b, n, h*64 + d]
#pragma unroll
    for (int a = 0; a < 4; a++) {
        float inv_l = 1.f / l[a];
#pragma unroll
        for (int c = 0; c < 4; c++)
            g_y[(base + q0 + r0 + a) * DMODEL + h * DHEAD + c0 + c] = acc[a][c] * inv_l;
    }
}

// ---------------------------------------------------------------------------
// Launch
// ---------------------------------------------------------------------------
extern "C" void kernel_launch(void* const* d_in, const int* in_sizes, int n_in,
                              void* d_out, int out_size) {
    const float* x     = (const float*)d_in[0];
    // d_in[1]: causal mask (bool) -- encoded analytically in attn_kernel
    const int*   pos   = (const int*)d_in[2];
    const float* qkv_w = (const float*)d_in[3];
    const float* out_w = (const float*)d_in[4];
    const float* qnw   = (const float*)d_in[5];
    const float* knw   = (const float*)d_in[6];
    float* out = (float*)d_out;

    float *qkv_buf, *y_buf;
    cudaGetSymbolAddress((void**)&qkv_buf, g_qkv);
    cudaGetSymbolAddress((void**)&y_buf, g_y);

    // 1) QKV projection: [4096,2048] @ [3072,2048]^T
    gemm_nt<<<dim3(QKV_DIM / 64, TOKENS / 64), 256>>>(x, qkv_w, qkv_buf,
                                                      TOKENS, QKV_DIM, DMODEL);
    // 2) RMSNorm + RoPE on q,k heads (in place)
    {
        int warps = TOKENS * NH_NORM;
        int threads = warps * 32;
        norm_rope_kernel<<<(threads + 255) / 256, 256>>>(pos, qnw, knw);
    }
    // 3) Causal GQA flash attention
    cudaFuncSetAttribute(attn_kernel, cudaFuncAttributeMaxDynamicSharedMemorySize,
                         ATTN_SMEM_BYTES);
    attn_kernel<<<dim3(N_SEQ / 64, HQ, B_SZ), 256, ATTN_SMEM_BYTES>>>();
    // 4) Output projection: [4096,2048] @ [2048,2048]^T
    gemm_nt<<<dim3(DMODEL / 64, TOKENS / 64), 256>>>(y_buf, out_w, out,
                                                     TOKENS, DMODEL, DMODEL);
}

// round 2
// speedup vs baseline: 1.7597x; 1.7597x over previous
#include <cuda_runtime.h>
#include <cuda_bf16.h>
#include <math_constants.h>
#include <cstdint>

// Problem constants
#define B_SZ    2
#define N_SEQ   2048
#define DMODEL  2048
#define HQ      32
#define HKV     8
#define DHEAD   64
#define QKV_DIM 3072          // DHEAD * (HQ + 2*HKV)
#define TOKENS  4096          // B_SZ * N_SEQ
#define NH_NORM (HQ + HKV)

// Scratch (allocation-free: device globals)
__device__ float g_qkv[(size_t)TOKENS * QKV_DIM];   // 48 MB
__device__ float g_y[(size_t)TOKENS * DMODEL];      // 32 MB

// ---------------------------------------------------------------------------
// TF32 tensor-core GEMM: C[M,N] = A[M,K] * B[N,K]^T (both K-major fp32)
// 128x128 block tile, BK=32, 256 threads (8 warps, 2x4), warp tile 64x32.
// mma.sync.m16n8k8 tf32. Tiles are staged into SMEM in *fragment order* so
// fragment loads are conflict-free vectorized LDS.
// ---------------------------------------------------------------------------
__device__ __forceinline__ uint32_t f2tf32(float f) {
    uint32_t u;
    asm("cvt.rna.tf32.f32 %0, %1;" : "=r"(u) : "f"(f));
    return u;
}

__device__ __forceinline__ void mma_tf32(float c[4], const uint32_t a[4],
                                         const uint32_t b[2]) {
    asm volatile(
        "mma.sync.aligned.m16n8k8.row.col.f32.tf32.tf32.f32 "
        "{%0,%1,%2,%3}, {%4,%5,%6,%7}, {%8,%9}, {%0,%1,%2,%3};\n"
        : "+f"(c[0]), "+f"(c[1]), "+f"(c[2]), "+f"(c[3])
        : "r"(a[0]), "r"(a[1]), "r"(a[2]), "r"(a[3]), "r"(b[0]), "r"(b[1]));
}

__global__ __launch_bounds__(256) void gemm_tf32(const float* __restrict__ A,
                                                 const float* __restrict__ Bm,
                                                 float* __restrict__ C,
                                                 int M, int N, int K) {
    // Fragment-ordered smem:
    //  Afr[(im*4+ik)*128 + lane*4 + j]  (8 m16-tiles x 4 k8-steps)
    //  Bfr[(in*4+ik)*64  + lane*2 + j]  (16 n8-tiles x 4 k8-steps)
    __shared__ uint32_t Afr[4096];
    __shared__ uint32_t Bfr[4096];

    const int tid = threadIdx.x;
    const int lane = tid & 31, warp = tid >> 5;
    const int wm = warp >> 2, wn = warp & 3;   // 2 x 4
    const size_t bm = (size_t)blockIdx.y * 128, bn = (size_t)blockIdx.x * 128;

    // staging coords: thread handles 4 float4s of each 128x32 tile
    int rowT[4], kqT[4];
#pragma unroll
    for (int s = 0; s < 4; s++) { int idx = tid + s * 256; rowT[s] = idx >> 3; kqT[s] = idx & 7; }

    const float* Abase = A + bm * K;
    const float* Bbase = Bm + bn * K;

    float4 ra[4], rb[4];
    float acc[4][4][4];
#pragma unroll
    for (int im = 0; im < 4; im++)
#pragma unroll
        for (int in = 0; in < 4; in++)
#pragma unroll
            for (int j = 0; j < 4; j++) acc[im][in][j] = 0.f;

#define LOADG(k0)                                                              \
    {                                                                          \
        _Pragma("unroll")                                                      \
        for (int s = 0; s < 4; s++) {                                          \
            ra[s] = *(const float4*)(Abase + (size_t)rowT[s] * K + (k0) + kqT[s] * 4); \
            rb[s] = *(const float4*)(Bbase + (size_t)rowT[s] * K + (k0) + kqT[s] * 4); \
        }                                                                      \
    }

#define STAGE()                                                                \
    {                                                                          \
        _Pragma("unroll")                                                      \
        for (int s = 0; s < 4; s++) {                                          \
            int row = rowT[s];                                                 \
            int g = row & 7, ishi = (row >> 3) & 1, im = row >> 4;             \
            const float* pv = (const float*)&ra[s];                            \
            const float* pw = (const float*)&rb[s];                            \
            _Pragma("unroll")                                                  \
            for (int e = 0; e < 4; e++) {                                      \
                int col = kqT[s] * 4 + e;                                      \
                int t = col & 3, hk = (col >> 2) & 1, ik = col >> 3;           \
                int ln = g * 4 + t;                                            \
                Afr[((im * 4 + ik) * 32 + ln) * 4 + (ishi + 2 * hk)] = f2tf32(pv[e]); \
                /* B: row is n index (tile is 128 n-rows) */                    \
                int inb = row >> 3, gb = row & 7;                              \
                Bfr[((inb * 4 + ik) * 32 + gb * 4 + t) * 2 + hk] = f2tf32(pw[e]); \
            }                                                                  \
        }                                                                      \
    }

    LOADG(0);
    STAGE();
    __syncthreads();

    for (int k0 = 32; k0 <= K; k0 += 32) {
        const bool more = (k0 < K);
        if (more) LOADG(k0);

#pragma unroll
        for (int ik = 0; ik < 4; ik++) {
            uint4 af[4];
            uint32_t bf[4][2];
#pragma unroll
            for (int im = 0; im < 4; im++)
                af[im] = *(const uint4*)&Afr[(((wm * 4 + im) * 4 + ik) * 32 + lane) * 4];
#pragma unroll
            for (int in = 0; in < 4; in++) {
                uint2 t = *(const uint2*)&Bfr[(((wn * 4 + in) * 4 + ik) * 32 + lane) * 2];
                bf[in][0] = t.x; bf[in][1] = t.y;
            }
#pragma unroll
            for (int im = 0; im < 4; im++) {
                const uint32_t a4[4] = {af[im].x, af[im].y, af[im].z, af[im].w};
#pragma unroll
                for (int in = 0; in < 4; in++)
                    mma_tf32(acc[im][in], a4, bf[in]);
            }
        }
        __syncthreads();
        if (more) {
            STAGE();
            __syncthreads();
        }
    }

    // Epilogue
#pragma unroll
    for (int im = 0; im < 4; im++) {
#pragma unroll
        for (int in = 0; in < 4; in++) {
            size_t r0 = bm + wm * 64 + im * 16 + (lane >> 2);
            size_t c0 = bn + wn * 32 + in * 8 + (lane & 3) * 2;
            *(float2*)&C[r0 * N + c0] = make_float2(acc[im][in][0], acc[im][in][1]);
            *(float2*)&C[(r0 + 8) * N + c0] = make_float2(acc[im][in][2], acc[im][in][3]);
        }
    }
#undef LOADG
#undef STAGE
}

// ---------------------------------------------------------------------------
// Fused per-head RMSNorm + RoPE, in place on g_qkv. One warp per (token, head).
// ---------------------------------------------------------------------------
__global__ void norm_rope_kernel(const int* __restrict__ pos,
                                 const float* __restrict__ qw,
                                 const float* __restrict__ kw) {
    int gw = (blockIdx.x * blockDim.x + threadIdx.x) >> 5;
    int lane = threadIdx.x & 31;
    if (gw >= TOKENS * NH_NORM) return;
    int token = gw / NH_NORM;
    int h = gw - token * NH_NORM;
    int p = pos[token & (N_SEQ - 1)];

    float* ptr = g_qkv + (size_t)token * QKV_DIM + h * DHEAD;
    float x1 = ptr[lane];
    float x2 = ptr[lane + 32];
    float ss = x1 * x1 + x2 * x2;
#pragma unroll
    for (int o = 16; o; o >>= 1) ss += __shfl_xor_sync(0xffffffffu, ss, o);
    float r = rsqrtf(ss * (1.0f / 64.0f) + 1e-6f);
    const float* w = (h < HQ) ? qw : kw;
    x1 *= r * w[lane];
    x2 *= r * w[lane + 32];

    float inv = expf(-(float)(2 * lane) * (9.210340371976184f / 64.0f));
    float sv, cv;
    sincosf((float)p * inv, &sv, &cv);
    ptr[lane]      = x1 * cv - x2 * sv;
    ptr[lane + 32] = x1 * sv + x2 * cv;
}

// ---------------------------------------------------------------------------
// Causal GQA flash attention, fp32 (unchanged from R1).
// ---------------------------------------------------------------------------
#define ATTN_SMEM_FLOATS (64 * 65 * 2 + 64 * 64 * 2)
#define ATTN_SMEM_BYTES  (ATTN_SMEM_FLOATS * 4)

__global__ __launch_bounds__(256) void attn_kernel() {
    extern __shared__ float sm[];
    float* Qs = sm;
    float* Ks = Qs + 64 * 65;
    float* Vs = Ks + 64 * 65;
    float* Ps = Vs + 64 * 64;

    int qb = blockIdx.x, h = blockIdx.y, b = blockIdx.z;
    int hk = h >> 2;
    int tid = threadIdx.x;
    int tx = tid & 15, ty = tid >> 4;
    int r0 = ty * 4, c0 = tx * 4;
    int q0 = qb * 64;
    size_t base = (size_t)b * N_SEQ;
    const float scale = 0.125f;

    for (int i = tid; i < 64 * 64; i += 256) {
        int row = i >> 6, d = i & 63;
        Qs[d * 65 + row] = g_qkv[(base + q0 + row) * QKV_DIM + h * DHEAD + d] * scale;
    }

    float m[4], l[4], acc[4][4];
#pragma unroll
    for (int a = 0; a < 4; a++) {
        m[a] = -CUDART_INF_F; l[a] = 0.f;
#pragma unroll
        for (int c = 0; c < 4; c++) acc[a][c] = 0.f;
    }

    for (int kb = 0; kb <= qb; kb++) {
        __syncthreads();
        for (int i = tid; i < 64 * 64; i += 256) {
            int row = i >> 6, d = i & 63;
            size_t toff = (base + kb * 64 + row) * QKV_DIM;
            Ks[d * 65 + row] = g_qkv[toff + (HQ + hk) * DHEAD + d];
            Vs[row * 64 + d] = g_qkv[toff + (HQ + HKV + hk) * DHEAD + d];
        }
        __syncthreads();

        float s4[4][4];
#pragma unroll
        for (int a = 0; a < 4; a++)
#pragma unroll
            for (int c = 0; c < 4; c++) s4[a][c] = 0.f;
#pragma unroll 4
        for (int d = 0; d < 64; d++) {
            float a0 = Qs[d * 65 + r0 + 0];
            float a1 = Qs[d * 65 + r0 + 1];
            float a2 = Qs[d * 65 + r0 + 2];
            float a3 = Qs[d * 65 + r0 + 3];
            float b0 = Ks[d * 65 + c0 + 0];
            float b1 = Ks[d * 65 + c0 + 1];
            float b2 = Ks[d * 65 + c0 + 2];
            float b3 = Ks[d * 65 + c0 + 3];
            s4[0][0] += a0 * b0; s4[0][1] += a0 * b1; s4[0][2] += a0 * b2; s4[0][3] += a0 * b3;
            s4[1][0] += a1 * b0; s4[1][1] += a1 * b1; s4[1][2] += a1 * b2; s4[1][3] += a1 * b3;
            s4[2][0] += a2 * b0; s4[2][1] += a2 * b1; s4[2][2] += a2 * b2; s4[2][3] += a2 * b3;
            s4[3][0] += a3 * b0; s4[3][1] += a3 * b1; s4[3][2] += a3 * b2; s4[3][3] += a3 * b3;
        }

        if (kb == qb) {
#pragma unroll
            for (int a = 0; a < 4; a++)
#pragma unroll
                for (int c = 0; c < 4; c++)
                    if (c0 + c > r0 + a) s4[a][c] = -1e30f;
        }

#pragma unroll
        for (int a = 0; a < 4; a++) {
            float mx = fmaxf(fmaxf(s4[a][0], s4[a][1]), fmaxf(s4[a][2], s4[a][3]));
#pragma unroll
            for (int o = 8; o; o >>= 1)
                mx = fmaxf(mx, __shfl_xor_sync(0xffffffffu, mx, o));
            float mn = fmaxf(m[a], mx);
            float corr = __expf(m[a] - mn);
            float sum = 0.f;
#pragma unroll
            for (int c = 0; c < 4; c++) {
                s4[a][c] = __expf(s4[a][c] - mn);
                sum += s4[a][c];
            }
#pragma unroll
            for (int o = 8; o; o >>= 1)
                sum += __shfl_xor_sync(0xffffffffu, sum, o);
            l[a] = l[a] * corr + sum;
            m[a] = mn;
#pragma unroll
            for (int c = 0; c < 4; c++) acc[a][c] *= corr;
#pragma unroll
            for (int c = 0; c < 4; c++) Ps[(r0 + a) * 64 + c0 + c] = s4[a][c];
        }
        __syncthreads();

#pragma unroll 4
        for (int j = 0; j < 64; j++) {
            float p0 = Ps[(r0 + 0) * 64 + j];
            float p1 = Ps[(r0 + 1) * 64 + j];
            float p2 = Ps[(r0 + 2) * 64 + j];
            float p3 = Ps[(r0 + 3) * 64 + j];
            float v0 = Vs[j * 64 + c0 + 0];
            float v1 = Vs[j * 64 + c0 + 1];
            float v2 = Vs[j * 64 + c0 + 2];
            float v3 = Vs[j * 64 + c0 + 3];
            acc[0][0] += p0 * v0; acc[0][1] += p0 * v1; acc[0][2] += p0 * v2; acc[0][3] += p0 * v3;
            acc[1][0] += p1 * v0; acc[1][1] += p1 * v1; acc[1][2] += p1 * v2; acc[1][3] += p1 * v3;
            acc[2][0] += p2 * v0; acc[2][1] += p2 * v1; acc[2][2] += p2 * v2; acc[2][3] += p2 * v3;
            acc[3][0] += p3 * v0; acc[3][1] += p3 * v1; acc[3][2] += p3 * v2; acc[3][3] += p3 * v3;
        }
    }

#pragma unroll
    for (int a = 0; a < 4; a++) {
        float inv_l = 1.f / l[a];
#pragma unroll
        for (int c = 0; c < 4; c++)
            g_y[(base + q0 + r0 + a) * DMODEL + h * DHEAD + c0 + c] = acc[a][c] * inv_l;
    }
}

// ---------------------------------------------------------------------------
// Launch
// ---------------------------------------------------------------------------
extern "C" void kernel_launch(void* const* d_in, const int* in_sizes, int n_in,
                              void* d_out, int out_size) {
    const float* x     = (const float*)d_in[0];
    const int*   pos   = (const int*)d_in[2];
    const float* qkv_w = (const float*)d_in[3];
    const float* out_w = (const float*)d_in[4];
    const float* qnw   = (const float*)d_in[5];
    const float* knw   = (const float*)d_in[6];
    float* out = (float*)d_out;

    float *qkv_buf, *y_buf;
    cudaGetSymbolAddress((void**)&qkv_buf, g_qkv);
    cudaGetSymbolAddress((void**)&y_buf, g_y);

    // 1) QKV projection: [4096,2048] @ [3072,2048]^T  (tf32 tensor cores)
    gemm_tf32<<<dim3(QKV_DIM / 128, TOKENS / 128), 256>>>(x, qkv_w, qkv_buf,
                                                          TOKENS, QKV_DIM, DMODEL);
    // 2) RMSNorm + RoPE
    {
        int warps = TOKENS * NH_NORM;
        int threads = warps * 32;
        norm_rope_kernel<<<(threads + 255) / 256, 256>>>(pos, qnw, knw);
    }
    // 3) Causal GQA flash attention (fp32)
    cudaFuncSetAttribute(attn_kernel, cudaFuncAttributeMaxDynamicSharedMemorySize,
                         ATTN_SMEM_BYTES);
    attn_kernel<<<dim3(N_SEQ / 64, HQ, B_SZ), 256, ATTN_SMEM_BYTES>>>();
    // 4) Output projection: [4096,2048] @ [2048,2048]^T  (tf32 tensor cores)
    gemm_tf32<<<dim3(DMODEL / 128, TOKENS / 128), 256>>>(y_buf, out_w, out,
                                                         TOKENS, DMODEL, DMODEL);
}

// round 3
// speedup vs baseline: 2.5863x; 1.4698x over previous
#include <cuda_runtime.h>
#include <cuda_bf16.h>
#include <math_constants.h>
#include <cstdint>

// Problem constants
#define B_SZ    2
#define N_SEQ   2048
#define DMODEL  2048
#define HQ      32
#define HKV     8
#define DHEAD   64
#define QKV_DIM 3072
#define TOKENS  4096
#define NH_NORM (HQ + HKV)

__device__ float g_qkv[(size_t)TOKENS * QKV_DIM];   // 48 MB
__device__ float g_y[(size_t)TOKENS * DMODEL];      // 32 MB

__device__ __forceinline__ uint32_t f2tf32(float f) {
    uint32_t u;
    asm("cvt.rna.tf32.f32 %0, %1;" : "=r"(u) : "f"(f));
    return u;
}

__device__ __forceinline__ void mma_tf32(float c[4], const uint32_t a[4],
                                         const uint32_t b[2]) {
    asm volatile(
        "mma.sync.aligned.m16n8k8.row.col.f32.tf32.tf32.f32 "
        "{%0,%1,%2,%3}, {%4,%5,%6,%7}, {%8,%9}, {%0,%1,%2,%3};\n"
        : "+f"(c[0]), "+f"(c[1]), "+f"(c[2]), "+f"(c[3])
        : "r"(a[0]), "r"(a[1]), "r"(a[2]), "r"(a[3]), "r"(b[0]), "r"(b[1]));
}

// ---------------------------------------------------------------------------
// TF32 GEMM: C[M,N] = A[M,K] * B[N,K]^T   (unchanged from R2)
// ---------------------------------------------------------------------------
__global__ __launch_bounds__(256) void gemm_tf32(const float* __restrict__ A,
                                                 const float* __restrict__ Bm,
                                                 float* __restrict__ C,
                                                 int M, int N, int K) {
    __shared__ uint32_t Afr[4096];
    __shared__ uint32_t Bfr[4096];

    const int tid = threadIdx.x;
    const int lane = tid & 31, warp = tid >> 5;
    const int wm = warp >> 2, wn = warp & 3;
    const size_t bm = (size_t)blockIdx.y * 128, bn = (size_t)blockIdx.x * 128;

    int rowT[4], kqT[4];
#pragma unroll
    for (int s = 0; s < 4; s++) { int idx = tid + s * 256; rowT[s] = idx >> 3; kqT[s] = idx & 7; }

    const float* Abase = A + bm * K;
    const float* Bbase = Bm + bn * K;

    float4 ra[4], rb[4];
    float acc[4][4][4];
#pragma unroll
    for (int im = 0; im < 4; im++)
#pragma unroll
        for (int in = 0; in < 4; in++)
#pragma unroll
            for (int j = 0; j < 4; j++) acc[im][in][j] = 0.f;

#define LOADG(k0)                                                              \
    {                                                                          \
        _Pragma("unroll")                                                      \
        for (int s = 0; s < 4; s++) {                                          \
            ra[s] = *(const float4*)(Abase + (size_t)rowT[s] * K + (k0) + kqT[s] * 4); \
            rb[s] = *(const float4*)(Bbase + (size_t)rowT[s] * K + (k0) + kqT[s] * 4); \
        }                                                                      \
    }

#define STAGE()                                                                \
    {                                                                          \
        _Pragma("unroll")                                                      \
        for (int s = 0; s < 4; s++) {                                          \
            int row = rowT[s];                                                 \
            int g = row & 7, ishi = (row >> 3) & 1, im = row >> 4;             \
            const float* pv = (const float*)&ra[s];                            \
            const float* pw = (const float*)&rb[s];                            \
            _Pragma("unroll")                                                  \
            for (int e = 0; e < 4; e++) {                                      \
                int col = kqT[s] * 4 + e;                                      \
                int t = col & 3, hk = (col >> 2) & 1, ik = col >> 3;           \
                int ln = g * 4 + t;                                            \
                Afr[((im * 4 + ik) * 32 + ln) * 4 + (ishi + 2 * hk)] = f2tf32(pv[e]); \
                int inb = row >> 3, gb = row & 7;                              \
                Bfr[((inb * 4 + ik) * 32 + gb * 4 + t) * 2 + hk] = f2tf32(pw[e]); \
            }                                                                  \
        }                                                                      \
    }

    LOADG(0);
    STAGE();
    __syncthreads();

    for (int k0 = 32; k0 <= K; k0 += 32) {
        const bool more = (k0 < K);
        if (more) LOADG(k0);

#pragma unroll
        for (int ik = 0; ik < 4; ik++) {
            uint4 af[4];
            uint32_t bf[4][2];
#pragma unroll
            for (int im = 0; im < 4; im++)
                af[im] = *(const uint4*)&Afr[(((wm * 4 + im) * 4 + ik) * 32 + lane) * 4];
#pragma unroll
            for (int in = 0; in < 4; in++) {
                uint2 tt = *(const uint2*)&Bfr[(((wn * 4 + in) * 4 + ik) * 32 + lane) * 2];
                bf[in][0] = tt.x; bf[in][1] = tt.y;
            }
#pragma unroll
            for (int im = 0; im < 4; im++) {
                const uint32_t a4[4] = {af[im].x, af[im].y, af[im].z, af[im].w};
#pragma unroll
                for (int in = 0; in < 4; in++)
                    mma_tf32(acc[im][in], a4, bf[in]);
            }
        }
        __syncthreads();
        if (more) {
            STAGE();
            __syncthreads();
        }
    }

#pragma unroll
    for (int im = 0; im < 4; im++) {
#pragma unroll
        for (int in = 0; in < 4; in++) {
            size_t r0 = bm + wm * 64 + im * 16 + (lane >> 2);
            size_t c0 = bn + wn * 32 + in * 8 + (lane & 3) * 2;
            *(float2*)&C[r0 * N + c0] = make_float2(acc[im][in][0], acc[im][in][1]);
            *(float2*)&C[(r0 + 8) * N + c0] = make_float2(acc[im][in][2], acc[im][in][3]);
        }
    }
#undef LOADG
#undef STAGE
}

// ---------------------------------------------------------------------------
// Fused per-head RMSNorm + RoPE (unchanged)
// ---------------------------------------------------------------------------
__global__ void norm_rope_kernel(const int* __restrict__ pos,
                                 const float* __restrict__ qw,
                                 const float* __restrict__ kw) {
    int gw = (blockIdx.x * blockDim.x + threadIdx.x) >> 5;
    int lane = threadIdx.x & 31;
    if (gw >= TOKENS * NH_NORM) return;
    int token = gw / NH_NORM;
    int h = gw - token * NH_NORM;
    int p = pos[token & (N_SEQ - 1)];

    float* ptr = g_qkv + (size_t)token * QKV_DIM + h * DHEAD;
    float x1 = ptr[lane];
    float x2 = ptr[lane + 32];
    float ss = x1 * x1 + x2 * x2;
#pragma unroll
    for (int o = 16; o; o >>= 1) ss += __shfl_xor_sync(0xffffffffu, ss, o);
    float r = rsqrtf(ss * (1.0f / 64.0f) + 1e-6f);
    const float* w = (h < HQ) ? qw : kw;
    x1 *= r * w[lane];
    x2 *= r * w[lane + 32];

    float inv = expf(-(float)(2 * lane) * (9.210340371976184f / 64.0f));
    float sv, cv;
    sincosf((float)p * inv, &sv, &cv);
    ptr[lane]      = x1 * cv - x2 * sv;
    ptr[lane + 32] = x1 * sv + x2 * cv;
}

// ---------------------------------------------------------------------------
// TF32 tensor-core causal GQA flash attention.
// Br=128 (8 warps x 16 rows), Bc=64. Q/K/V staged fragment-order (swizzled),
// P staged per-warp in A-fragment order. m16n8k8 tf32 mma.
// ---------------------------------------------------------------------------
#define ATTN_SMEM_WORDS (8192 + 4096 + 4096 + 8192)
#define ATTN_SMEM_BYTES (ATTN_SMEM_WORDS * 4)

__global__ __launch_bounds__(256) void attn_mma() {
    extern __shared__ uint32_t smu[];
    uint32_t* Qfr = smu;             // 8192: [(w*8+ik)*32 + slot]*4 + reg
    uint32_t* Kfr = smu + 8192;      // 4096: [(in*8+ik)*32 + slot]*2 + reg
    uint32_t* Vfr = smu + 12288;     // 4096: [(ik*8+dt)*32 + slot]*2 + reg
    uint32_t* Pfr = smu + 16384;     // 8192: per-warp 1024

    int qb = (gridDim.x - 1) - blockIdx.x;   // big tiles first
    int h = blockIdx.y, b = blockIdx.z;
    int hk = h >> 2;
    int tid = threadIdx.x, lane = tid & 31, w = tid >> 5;
    int g = lane >> 2, t = lane & 3;
    size_t base = (size_t)b * N_SEQ;
    int q0 = qb * 128;

    // ---- stage Q tile (pre-scaled), fragment order + swizzle ----
#pragma unroll
    for (int s = 0; s < 8; s++) {
        int idx = tid + s * 256;
        int row = idx >> 4, f4 = idx & 15, d0 = f4 * 4;
        float4 v = *(const float4*)&g_qkv[(base + q0 + row) * QKV_DIM + h * DHEAD + d0];
        int wq = row >> 4, ishi = (row >> 3) & 1, gq = row & 7;
#pragma unroll
        for (int e = 0; e < 4; e++) {
            int d = d0 + e;
            int ik = d >> 3;
            int slot = (gq * 4 + (d & 3)) ^ ((ik & 3) * 4);
            Qfr[((wq * 8 + ik) * 32 + slot) * 4 + ishi + 2 * ((d >> 2) & 1)] =
                f2tf32(((const float*)&v)[e] * 0.125f);
        }
    }

    float4 rk[4], rv[4];
    const int nb = 2 * qb + 2;

#define LOADKV(kb_)                                                            \
    {                                                                          \
        int k0_ = (kb_) * 64;                                                  \
        _Pragma("unroll")                                                      \
        for (int s = 0; s < 4; s++) {                                          \
            int idx = tid + s * 256;                                           \
            int key = idx >> 4, f4 = idx & 15;                                 \
            size_t toff = (base + k0_ + key) * QKV_DIM;                        \
            rk[s] = *(const float4*)&g_qkv[toff + (HQ + hk) * DHEAD + f4 * 4]; \
            rv[s] = *(const float4*)&g_qkv[toff + (HQ + HKV + hk) * DHEAD + f4 * 4]; \
        }                                                                      \
    }

#define STAGEKV()                                                              \
    {                                                                          \
        _Pragma("unroll")                                                      \
        for (int s = 0; s < 4; s++) {                                          \
            int idx = tid + s * 256;                                           \
            int key = idx >> 4, f4 = idx & 15;                                 \
            _Pragma("unroll")                                                  \
            for (int e = 0; e < 4; e++) {                                      \
                int d = f4 * 4 + e;                                            \
                int ik = d >> 3, in = key >> 3;                                \
                int slK = ((key & 7) * 4 + (d & 3)) ^ ((ik & 3) * 4);          \
                Kfr[((in * 8 + ik) * 32 + slK) * 2 + ((d >> 2) & 1)] =         \
                    f2tf32(((const float*)&rk[s])[e]);                         \
                int dt = d >> 3, ikk = key >> 3;                               \
                int slV = ((d & 7) * 4 + (key & 3)) ^ ((dt & 3) * 4);          \
                Vfr[((ikk * 8 + dt) * 32 + slV) * 2 + ((key >> 2) & 1)] =      \
                    f2tf32(((const float*)&rv[s])[e]);                         \
            }                                                                  \
        }                                                                      \
    }

    float m0 = -CUDART_INF_F, m1 = -CUDART_INF_F, l0 = 0.f, l1 = 0.f;
    float o[8][4];
#pragma unroll
    for (int dt = 0; dt < 8; dt++)
#pragma unroll
        for (int j = 0; j < 4; j++) o[dt][j] = 0.f;

    uint32_t* Pw = Pfr + w * 1024;
    const int row0 = q0 + w * 16 + g;

    LOADKV(0);

    for (int kb = 0; kb < nb; kb++) {
        if (kb > 0) __syncthreads();   // all PV reads of prev Kfr/Vfr done
        STAGEKV();
        __syncthreads();
        if (kb + 1 < nb) LOADKV(kb + 1);

        // ---- S = Q K^T ----
        float sacc[8][4];
#pragma unroll
        for (int n = 0; n < 8; n++)
#pragma unroll
            for (int j = 0; j < 4; j++) sacc[n][j] = 0.f;

#pragma unroll
        for (int ik = 0; ik < 8; ik++) {
            uint4 aq = *(const uint4*)&Qfr[((w * 8 + ik) * 32 + (lane ^ ((ik & 3) * 4))) * 4];
            const uint32_t a4[4] = {aq.x, aq.y, aq.z, aq.w};
#pragma unroll
            for (int n = 0; n < 8; n++) {
                uint2 bk = *(const uint2*)&Kfr[((n * 8 + ik) * 32 + (lane ^ ((ik & 3) * 4))) * 2];
                const uint32_t b2[2] = {bk.x, bk.y};
                mma_tf32(sacc[n], a4, b2);
            }
        }

        // ---- causal mask (only diagonal-overlapping blocks) ----
        if (kb >= 2 * qb) {
            int k0 = kb * 64;
#pragma unroll
            for (int n = 0; n < 8; n++) {
                int cb = k0 + n * 8 + 2 * t;
                if (cb > row0)     sacc[n][0] = -1e30f;
                if (cb + 1 > row0) sacc[n][1] = -1e30f;
                if (cb > row0 + 8)     sacc[n][2] = -1e30f;
                if (cb + 1 > row0 + 8) sacc[n][3] = -1e30f;
            }
        }

        // ---- online softmax (rows g and g+8; quad reduction) ----
        float mx0 = -1e30f, mx1 = -1e30f;
#pragma unroll
        for (int n = 0; n < 8; n++) {
            mx0 = fmaxf(mx0, fmaxf(sacc[n][0], sacc[n][1]));
            mx1 = fmaxf(mx1, fmaxf(sacc[n][2], sacc[n][3]));
        }
        mx0 = fmaxf(mx0, __shfl_xor_sync(0xffffffffu, mx0, 1));
        mx0 = fmaxf(mx0, __shfl_xor_sync(0xffffffffu, mx0, 2));
        mx1 = fmaxf(mx1, __shfl_xor_sync(0xffffffffu, mx1, 1));
        mx1 = fmaxf(mx1, __shfl_xor_sync(0xffffffffu, mx1, 2));

        float mn0 = fmaxf(m0, mx0), mn1 = fmaxf(m1, mx1);
        float c0 = __expf(m0 - mn0), c1 = __expf(m1 - mn1);
        float s0 = 0.f, s1 = 0.f;
#pragma unroll
        for (int n = 0; n < 8; n++) {
            sacc[n][0] = __expf(sacc[n][0] - mn0);
            sacc[n][1] = __expf(sacc[n][1] - mn0);
            sacc[n][2] = __expf(sacc[n][2] - mn1);
            sacc[n][3] = __expf(sacc[n][3] - mn1);
            s0 += sacc[n][0] + sacc[n][1];
            s1 += sacc[n][2] + sacc[n][3];
        }
        s0 += __shfl_xor_sync(0xffffffffu, s0, 1);
        s0 += __shfl_xor_sync(0xffffffffu, s0, 2);
        s1 += __shfl_xor_sync(0xffffffffu, s1, 1);
        s1 += __shfl_xor_sync(0xffffffffu, s1, 2);
        l0 = l0 * c0 + s0; l1 = l1 * c1 + s1;
        m0 = mn0; m1 = mn1;
#pragma unroll
        for (int dt = 0; dt < 8; dt++) {
            o[dt][0] *= c0; o[dt][1] *= c0;
            o[dt][2] *= c1; o[dt][3] *= c1;
        }

        // ---- write P as A-fragments (per-warp private) ----
#pragma unroll
        for (int n = 0; n < 8; n++) {
            int ca = 2 * t, cb = 2 * t + 1;
            Pw[(n * 32 + g * 4 + (ca & 3)) * 4 + 0 + 2 * (ca >> 2)] = f2tf32(sacc[n][0]);
            Pw[(n * 32 + g * 4 + (cb & 3)) * 4 + 0 + 2 * (cb >> 2)] = f2tf32(sacc[n][1]);
            Pw[(n * 32 + g * 4 + (ca & 3)) * 4 + 1 + 2 * (ca >> 2)] = f2tf32(sacc[n][2]);
            Pw[(n * 32 + g * 4 + (cb & 3)) * 4 + 1 + 2 * (cb >> 2)] = f2tf32(sacc[n][3]);
        }
        __syncwarp();

        // ---- O += P V ----
#pragma unroll
        for (int ik = 0; ik < 8; ik++) {
            uint4 ap = *(const uint4*)&Pw[(ik * 32 + lane) * 4];
            const uint32_t a4[4] = {ap.x, ap.y, ap.z, ap.w};
#pragma unroll
            for (int dt = 0; dt < 8; dt++) {
                uint2 bv = *(const uint2*)&Vfr[((ik * 8 + dt) * 32 + (lane ^ ((dt & 3) * 4))) * 2];
                const uint32_t b2[2] = {bv.x, bv.y};
                mma_tf32(o[dt], a4, b2);
            }
        }
    }

    // ---- epilogue ----
    float i0 = 1.f / l0, i1 = 1.f / l1;
#pragma unroll
    for (int dt = 0; dt < 8; dt++) {
        int col = h * DHEAD + dt * 8 + 2 * t;
        *(float2*)&g_y[(base + row0) * DMODEL + col] = make_float2(o[dt][0] * i0, o[dt][1] * i0);
        *(float2*)&g_y[(base + row0 + 8) * DMODEL + col] = make_float2(o[dt][2] * i1, o[dt][3] * i1);
    }
#undef LOADKV
#undef STAGEKV
}

// ---------------------------------------------------------------------------
// Launch
// ---------------------------------------------------------------------------
extern "C" void kernel_launch(void* const* d_in, const int* in_sizes, int n_in,
                              void* d_out, int out_size) {
    const float* x     = (const float*)d_in[0];
    const int*   pos   = (const int*)d_in[2];
    const float* qkv_w = (const float*)d_in[3];
    const float* out_w = (const float*)d_in[4];
    const float* qnw   = (const float*)d_in[5];
    const float* knw   = (const float*)d_in[6];
    float* out = (float*)d_out;

    float *qkv_buf, *y_buf;
    cudaGetSymbolAddress((void**)&qkv_buf, g_qkv);
    cudaGetSymbolAddress((void**)&y_buf, g_y);

    gemm_tf32<<<dim3(QKV_DIM / 128, TOKENS / 128), 256>>>(x, qkv_w, qkv_buf,
                                                          TOKENS, QKV_DIM, DMODEL);
    {
        int warps = TOKENS * NH_NORM;
        int threads = warps * 32;
        norm_rope_kernel<<<(threads + 255) / 256, 256>>>(pos, qnw, knw);
    }
    cudaFuncSetAttribute(attn_mma, cudaFuncAttributeMaxDynamicSharedMemorySize,
                         ATTN_SMEM_BYTES);
    attn_mma<<<dim3(N_SEQ / 128, HQ, B_SZ), 256, ATTN_SMEM_BYTES>>>();
    gemm_tf32<<<dim3(DMODEL / 128, TOKENS / 128), 256>>>(y_buf, out_w, out,
                                                         TOKENS, DMODEL, DMODEL);
}